// round 7
// baseline (speedup 1.0000x reference)
#include <cuda_runtime.h>
#include <cuda_bf16.h>

// WTA / row-wise top-k(=64) scatter-to-dense, exact incl. stable tie-breaking.
// 2 rows per CTA (TPB=512), software-pipelined: both rows' loads issued up
// front; row B's data streams in while row A is histogrammed/selected/stored.
// Per row fast path (valid when count(f>=1.5) >= k; true for N(0,1) rows):
//   (1) fused histogram of (bits>>16)-0x3FC0 over f >= 1.5 with per-bin
//       slot capture of full bits ([1.5,6) spans exactly 256 bins)
//   (2) warp0: pick bin where reverse-cumulative crosses k, shuffle-rank the
//       <=16 captured elements -> exact k-th value + tie metadata
//   (3) output: out = (f >= thr) ? f : 0 ; rare stable tie-break by column.
// Generic fallback (cold, exact): 4-pass 256-bin radix select over fmap keys.

#define COLS  8192
#define TPB   512
#define VPT   4                    // float4 per thread per row
#define NW    (TPB / 32)
#define SLOTS 16
#define FULL  0xffffffffu

__device__ __forceinline__ unsigned fmap_u(unsigned b) {
    return b ^ ((unsigned)((int)b >> 31) | 0x80000000u);
}
__device__ __forceinline__ float funmap(unsigned v) {
    unsigned mask = ((unsigned)((int)(~v) >> 31)) | 0x80000000u;
    return __uint_as_float(v ^ mask);
}

struct SelScal { unsigned thr, need, eq, flag, sel; };

// (1) fused histogram + slot capture for one row held in registers
__device__ __forceinline__ void hist_capture(const float4* v, unsigned* H,
                                             unsigned* S)
{
#pragma unroll
    for (int j = 0; j < VPT; j++) {
#pragma unroll
        for (int c = 0; c < 4; c++) {
            const float f = (c == 0) ? v[j].x : (c == 1) ? v[j].y
                          : (c == 2) ? v[j].z : v[j].w;
            if (f >= 1.5f) {
                const unsigned bits = __float_as_uint(f);
                unsigned b = (bits >> 16) - 0x3FC0u;
                b = min(b, 255u);
                const unsigned p = atomicAdd(&H[b], 1u);
                if (p < SLOTS) S[(b << 4) + p] = bits;
            }
        }
    }
}

// (2) warp0-only: bin select + in-bin shuffle rank
__device__ __forceinline__ void warp0_select(unsigned k, const unsigned* H,
                                             const unsigned* S, SelScal* sc,
                                             int lane)
{
    unsigned hv8[8], tot[8];
#pragma unroll
    for (int c = 0; c < 8; c++) {
        hv8[c] = H[c * 32 + lane];
        tot[c] = __reduce_add_sync(FULL, hv8[c]);
    }
    unsigned suf = 0u, tch = 0u, exC = 0u;
#pragma unroll
    for (int c = 7; c >= 0; c--) {
        if (suf < k && k <= suf + tot[c]) { tch = (unsigned)c; exC = suf; }
        suf += tot[c];
    }
    if (suf < k) {
        if (lane == 0) sc->flag = 1u;
        return;
    }
    const unsigned hv = hv8[tch];
    unsigned incl = hv;                   // suffix sum over higher bins
#pragma unroll
    for (int o = 1; o < 32; o <<= 1) {
        const unsigned n = __shfl_down_sync(FULL, incl, o);
        if (lane + o < 32) incl += n;
    }
    const unsigned excl = incl - hv;
    const bool fired = (exC + excl < k) && (k <= exC + incl);
    const unsigned fm = __ballot_sync(FULL, fired);
    const int src = __ffs(fm) - 1;
    const unsigned selBin = tch * 32u + (unsigned)src;
    const unsigned need1  = k - exC - __shfl_sync(FULL, excl, src);
    const unsigned E      = __shfl_sync(FULL, hv, src);
    if (E > SLOTS) {
        if (lane == 0) sc->flag = 1u;
        return;
    }
    const unsigned key = (lane < (int)E) ? S[(selBin << 4) + lane] : 0u;
    unsigned gt = 0u, eq = 0u;
#pragma unroll
    for (int o = 0; o < SLOTS; o++) {
        const unsigned other = __shfl_sync(FULL, key, o);
        if (o < (int)E) {
            gt += (other > key) ? 1u : 0u;
            eq += (other == key) ? 1u : 0u;
        }
    }
    if (gt < need1 && need1 <= gt + eq) {   // unique key fires
        sc->thr  = key;
        sc->need = need1 - gt;
        sc->eq   = eq;
    }
}

// generic fallback: 4-pass 256-bin radix over fmap keys (CTA-wide, cold)
__device__ __forceinline__ void fallback_radix(const float4* v, unsigned k,
                                               unsigned* H, SelScal* sc,
                                               int tid, int lane, int warp,
                                               float* thrF, unsigned* need,
                                               unsigned* eqCnt)
{
    unsigned prefix = 0u, nd = k;
#pragma unroll 1
    for (int p = 3; p >= 0; p--) {
        const int sh = 8 * p;
        __syncthreads();
        if (tid < 256) H[tid] = 0u;
        __syncthreads();
#pragma unroll 1
        for (int j = 0; j < VPT; j++) {
            const float e[4] = { v[j].x, v[j].y, v[j].z, v[j].w };
#pragma unroll
            for (int c = 0; c < 4; c++) {
                const unsigned key = fmap_u(__float_as_uint(e[c]));
                const bool m = (p == 3) || (((key ^ prefix) >> (sh + 8)) == 0u);
                if (m) atomicAdd(&H[(key >> sh) & 255u], 1u);
            }
        }
        __syncthreads();
        if (warp == 0) {
            unsigned hv8[8], tot[8];
#pragma unroll
            for (int c = 0; c < 8; c++) {
                hv8[c] = H[c * 32 + lane];
                tot[c] = __reduce_add_sync(FULL, hv8[c]);
            }
            unsigned suf = 0u, tch = 0u, exC = 0u;
#pragma unroll
            for (int c = 7; c >= 0; c--) {
                if (suf < nd && nd <= suf + tot[c]) { tch = (unsigned)c; exC = suf; }
                suf += tot[c];
            }
            const unsigned hv = hv8[tch];
            unsigned incl = hv;
#pragma unroll
            for (int o = 1; o < 32; o <<= 1) {
                const unsigned n = __shfl_down_sync(FULL, incl, o);
                if (lane + o < 32) incl += n;
            }
            const unsigned excl = incl - hv;
            if (exC + excl < nd && nd <= exC + incl) {
                sc->sel  = tch * 32 + (unsigned)lane;
                sc->need = nd - exC - excl;
                sc->eq   = hv;
            }
        }
        __syncthreads();
        prefix |= sc->sel << sh;
        nd = sc->need;
    }
    *eqCnt = sc->eq;
    *need  = nd;
    *thrF  = funmap(prefix);
}

// (3) output one row; rare stable tie-break (CTA-uniform branch)
__device__ __forceinline__ void output_row(const float4* v, float thrF,
                                           unsigned need, unsigned eqCnt,
                                           float4* __restrict__ o4,
                                           size_t base, unsigned* sWsum,
                                           int lane, int warp)
{
    if (need == eqCnt) {
#pragma unroll
        for (int j = 0; j < VPT; j++) {
            float4 o;
            o.x = (v[j].x >= thrF) ? v[j].x : 0.0f;
            o.y = (v[j].y >= thrF) ? v[j].y : 0.0f;
            o.z = (v[j].z >= thrF) ? v[j].z : 0.0f;
            o.w = (v[j].w >= thrF) ? v[j].w : 0.0f;
            __stcs(&o4[base + (size_t)j * TPB], o);
        }
    } else {
        unsigned keepMask = 0u, running = 0u;
#pragma unroll 1
        for (int j = 0; j < VPT; j++) {
            const float e[4] = { v[j].x, v[j].y, v[j].z, v[j].w };
            unsigned eq[4], lc = 0u;
#pragma unroll
            for (int c = 0; c < 4; c++) {
                eq[c] = (e[c] == thrF) ? 1u : 0u;
                lc += eq[c];
            }
            unsigned pre = lc;
#pragma unroll
            for (int o = 1; o < 32; o <<= 1) {
                const unsigned n = __shfl_up_sync(FULL, pre, o);
                if (lane >= o) pre += n;
            }
            const unsigned excl = pre - lc;
            __syncthreads();
            if (lane == 31) sWsum[warp] = pre;
            __syncthreads();
            unsigned off = 0u, tot = 0u;
#pragma unroll
            for (int w = 0; w < NW; w++) {
                const unsigned t = sWsum[w];
                if (w < warp) off += t;
                tot += t;
            }
            unsigned r = running + off + excl;
#pragma unroll
            for (int c = 0; c < 4; c++) {
                if (eq[c]) {
                    if (r < need) keepMask |= 1u << (4 * j + c);
                    r++;
                }
            }
            running += tot;
        }
#pragma unroll
        for (int j = 0; j < VPT; j++) {
            const float e[4] = { v[j].x, v[j].y, v[j].z, v[j].w };
            float o[4];
#pragma unroll
            for (int c = 0; c < 4; c++) {
                const int i = 4 * j + c;
                const bool keep = (e[c] > thrF) ||
                                  ((e[c] == thrF) && ((keepMask >> i) & 1u));
                o[c] = keep ? e[c] : 0.0f;
            }
            float4 ov = { o[0], o[1], o[2], o[3] };
            __stcs(&o4[base + (size_t)j * TPB], ov);
        }
    }
}

__global__ __launch_bounds__(TPB, 2)
void wta_topk_kernel(const float4* __restrict__ x4,
                     const int*    __restrict__ kp,
                     float4*       __restrict__ o4)
{
    __shared__ unsigned sHist[2 * 256];
    __shared__ unsigned sBin[2 * 256 * SLOTS];
    __shared__ unsigned sWsum[NW];
    __shared__ SelScal  sc;

    unsigned* HA = sHist;          unsigned* HB = sHist + 256;
    unsigned* SA = sBin;           unsigned* SB = sBin + 256 * SLOTS;

    const int tid  = threadIdx.x;
    const int lane = tid & 31;
    const int warp = tid >> 5;
    const size_t baseA = (size_t)(2 * blockIdx.x)     * (COLS / 4) + tid;
    const size_t baseB = (size_t)(2 * blockIdx.x + 1) * (COLS / 4) + tid;

    // ---- issue ALL loads up front (rows A and B; 8 LDG.128 in flight) ----
    float4 vA[VPT], vB[VPT];
#pragma unroll
    for (int j = 0; j < VPT; j++) vA[j] = __ldcs(&x4[baseA + (size_t)j * TPB]);
#pragma unroll
    for (int j = 0; j < VPT; j++) vB[j] = __ldcs(&x4[baseB + (size_t)j * TPB]);
    const unsigned k = (unsigned)__ldg(kp);

    sHist[tid] = 0u;               // zeros both HA and HB (512 entries)
    if (tid == 0) sc.flag = 0u;
    __syncthreads();                                              // S1

    // ---- row A: hist (waits only on vA) ----
    hist_capture(vA, HA, SA);
    __syncthreads();                                              // S2
    if (warp == 0) warp0_select(k, HA, SA, &sc, lane);
    __syncthreads();                                              // S3

    float thrA; unsigned needA, eqA;
    if (sc.flag == 0u) {
        thrA = __uint_as_float(sc.thr); needA = sc.need; eqA = sc.eq;
    } else {
        fallback_radix(vA, k, HA, &sc, tid, lane, warp, &thrA, &needA, &eqA);
        __syncthreads();
        if (tid == 0) sc.flag = 0u;        // reset for row B
        __syncthreads();
    }

    // ---- overlap: row B hist + row A output ----
    hist_capture(vB, HB, SB);              // vB arrived during A's phases
    output_row(vA, thrA, needA, eqA, o4, baseA, sWsum, lane, warp);
    __syncthreads();                                              // S4

    if (warp == 0) warp0_select(k, HB, SB, &sc, lane);
    __syncthreads();                                              // S5

    float thrB; unsigned needB, eqB;
    if (sc.flag == 0u) {
        thrB = __uint_as_float(sc.thr); needB = sc.need; eqB = sc.eq;
    } else {
        fallback_radix(vB, k, HB, &sc, tid, lane, warp, &thrB, &needB, &eqB);
        __syncthreads();
    }
    output_row(vB, thrB, needB, eqB, o4, baseB, sWsum, lane, warp);
}

extern "C" void kernel_launch(void* const* d_in, const int* in_sizes, int n_in,
                              void* d_out, int out_size) {
    const float4* x4 = (const float4*)d_in[0];
    const int*    kp = (const int*)d_in[1];
    float4*       o4 = (float4*)d_out;
    const int rows = in_sizes[0] / COLS;
    wta_topk_kernel<<<rows / 2, TPB>>>(x4, kp, o4);
}